// round 10
// baseline (speedup 1.0000x reference)
#include <cuda_runtime.h>

#define BATCH 2048
#define T 128
#define NS 16
#define MS 8
#define CS 4
#define DT 0.01f

// Batch-independent tables (L2-resident).
__device__ float g_K2[T * NS * MS];             // K[t][i][q]
__device__ float g_Pf[(T - 1) * NS * NS];       // P_f[t]
__device__ float g_M[T * NS * NS];              // M[t][i][j] = ((I-KH)F)
__device__ float g_N[T * NS * CS];              // N[t][i][c] = ((I-KH)*DT*Bc)
__device__ float g_G[(T - 1) * NS * NS];        // G[t][i][j]
__device__ float g_U[(T - 1) * NS * NS];        // U[t] = I - G F
__device__ float g_V[(T - 1) * NS * CS];        // V[t] = G * DT * Bc
__device__ float g_B[(size_t)BATCH * (T - 1) * NS];  // b[b][t][i]

__device__ __forceinline__ float4 ld4(const float* p) { return *reinterpret_cast<const float4*>(p); }
__device__ __forceinline__ void st4(float* p, float4 v) { *reinterpret_cast<float4*>(p) = v; }
__device__ __forceinline__ float rcpa(float x) { float y; asm("rcp.approx.f32 %0, %1;" : "=f"(y) : "f"(x)); return y; }
__device__ __forceinline__ float shfl(float v, int s) { return __shfl_sync(0xffffffffu, v, s); }
__device__ __forceinline__ float shflx(float v, int m) { return __shfl_xor_sync(0xffffffffu, v, m); }
__device__ __forceinline__ float shfl16(float v, int s) { return __shfl_sync(0xffffffffu, v, s, 16); }

// ============================================================================
// Kernel A: Riccati recursion (ONE warp). Produces g_K2, g_Pf.
// ============================================================================
__global__ __launch_bounds__(32) void kf_gains(
    const float* __restrict__ P0, const float* __restrict__ A,
    const float* __restrict__ H, const float* __restrict__ Q,
    const float* __restrict__ R)
{
    __shared__ float Fb[16 * 20], Ftb[16 * 20], Qb[16 * 20];
    __shared__ float Hb[8 * 20], Ht[16 * 8], Rb[64];
    __shared__ float P[16 * 20], PHt[16 * 8], X2[8 * 20];

    const int lane = threadIdx.x;
    for (int idx = lane; idx < 256; idx += 32) {
        int i = idx >> 4, k = idx & 15;
        float a = A[idx];
        float f = (i == k ? 1.0f : 0.0f) + DT * a;
        Fb[i * 20 + k] = f; Ftb[k * 20 + i] = f;
        Qb[i * 20 + k] = Q[idx];
        P[i * 20 + k] = P0[idx];
    }
    for (int idx = lane; idx < 128; idx += 32) {
        int q = idx >> 4, k = idx & 15;
        float h = H[idx];
        Hb[q * 20 + k] = h; Ht[k * 8 + q] = h;
    }
    for (int idx = lane; idx < 64; idx += 32) Rb[idx] = R[idx];
    __syncwarp();

    const int row = lane >> 1, h = lane & 1, j0 = h * 8;
    const int rr = row & 7;

    float frow[16];
    #pragma unroll
    for (int k = 0; k < 16; ++k) frow[k] = Fb[row * 20 + k];

    float a[8], w[8];

    for (int t = 0; t < T; ++t) {
        // W = F * P
        #pragma unroll
        for (int j = 0; j < 8; ++j) w[j] = 0.0f;
        #pragma unroll
        for (int k = 0; k < 16; ++k) {
            float fv = frow[k];
            float4 p0 = ld4(&P[k * 20 + j0]);
            float4 p1 = ld4(&P[k * 20 + j0 + 4]);
            w[0] = fmaf(fv, p0.x, w[0]); w[1] = fmaf(fv, p0.y, w[1]);
            w[2] = fmaf(fv, p0.z, w[2]); w[3] = fmaf(fv, p0.w, w[3]);
            w[4] = fmaf(fv, p1.x, w[4]); w[5] = fmaf(fv, p1.y, w[5]);
            w[6] = fmaf(fv, p1.z, w[6]); w[7] = fmaf(fv, p1.w, w[7]);
        }

        // PP = W * F^T + Q  (regs a[])
        {
            float wk[16];
            #pragma unroll
            for (int j = 0; j < 8; ++j) {
                wk[j0 + j] = w[j];
                wk[(j0 ^ 8) + j] = shflx(w[j], 1);
            }
            float4 q0 = ld4(&Qb[row * 20 + j0]);
            float4 q1 = ld4(&Qb[row * 20 + j0 + 4]);
            a[0] = q0.x; a[1] = q0.y; a[2] = q0.z; a[3] = q0.w;
            a[4] = q1.x; a[5] = q1.y; a[6] = q1.z; a[7] = q1.w;
            #pragma unroll
            for (int k = 0; k < 16; ++k) {
                float wv = wk[k];
                float4 f0 = ld4(&Ftb[k * 20 + j0]);
                float4 f1 = ld4(&Ftb[k * 20 + j0 + 4]);
                a[0] = fmaf(wv, f0.x, a[0]); a[1] = fmaf(wv, f0.y, a[1]);
                a[2] = fmaf(wv, f0.z, a[2]); a[3] = fmaf(wv, f0.w, a[3]);
                a[4] = fmaf(wv, f1.x, a[4]); a[5] = fmaf(wv, f1.y, a[5]);
                a[6] = fmaf(wv, f1.z, a[6]); a[7] = fmaf(wv, f1.w, a[7]);
            }
        }

        // PHt[i][q] = sum_k PP[i][k] * H[q][k]
        {
            float pk[16];
            #pragma unroll
            for (int j = 0; j < 8; ++j) {
                pk[j0 + j] = a[j];
                pk[(j0 ^ 8) + j] = shflx(a[j], 1);
            }
            const int qh = h * 4;
            float4 acc = make_float4(0.f, 0.f, 0.f, 0.f);
            #pragma unroll
            for (int k = 0; k < 16; ++k) {
                float p = pk[k];
                float4 hv = ld4(&Ht[k * 8 + qh]);
                acc.x = fmaf(p, hv.x, acc.x); acc.y = fmaf(p, hv.y, acc.y);
                acc.z = fmaf(p, hv.z, acc.z); acc.w = fmaf(p, hv.w, acc.w);
            }
            st4(&PHt[row * 8 + qh], acc);
        }
        __syncwarp();

        // S rows + RHS into registers
        float s4[4], rhs[8];
        {
            const int ch = h * 4;
            s4[0] = Rb[rr * 8 + ch];     s4[1] = Rb[rr * 8 + ch + 1];
            s4[2] = Rb[rr * 8 + ch + 2]; s4[3] = Rb[rr * 8 + ch + 3];
            #pragma unroll
            for (int k = 0; k < 16; ++k) {
                float hv = Hb[rr * 20 + k];
                float4 ph = ld4(&PHt[k * 8 + ch]);
                s4[0] = fmaf(hv, ph.x, s4[0]); s4[1] = fmaf(hv, ph.y, s4[1]);
                s4[2] = fmaf(hv, ph.z, s4[2]); s4[3] = fmaf(hv, ph.w, s4[3]);
            }
            #pragma unroll
            for (int j = 0; j < 8; ++j)
                rhs[j] = PHt[(h * 8 + j) * 8 + rr];
        }

        // GJ solve S * X2 = PHt^T (8x8); K = X2^T
        {
            #pragma unroll
            for (int p = 0; p < 8; ++p) {
                const int hp = (p >= 4) ? 1 : 0;
                float cand = s4[p & 3];
                float f_num = shfl(cand, (rr << 1) | hp);
                float diag  = shfl(cand, (p << 1) | hp);
                const int src = (p << 1) | h;
                float ps0 = shfl(s4[0], src), ps1 = shfl(s4[1], src);
                float ps2 = shfl(s4[2], src), ps3 = shfl(s4[3], src);
                float pr[8];
                #pragma unroll
                for (int j = 0; j < 8; ++j) pr[j] = shfl(rhs[j], src);
                float f = (rr == p) ? 0.0f : f_num * rcpa(diag);
                s4[0] = fmaf(-f, ps0, s4[0]); s4[1] = fmaf(-f, ps1, s4[1]);
                s4[2] = fmaf(-f, ps2, s4[2]); s4[3] = fmaf(-f, ps3, s4[3]);
                #pragma unroll
                for (int j = 0; j < 8; ++j) rhs[j] = fmaf(-f, pr[j], rhs[j]);
            }
            float s01 = (rr & 1) ? s4[1] : s4[0];
            float s23 = (rr & 1) ? s4[3] : s4[2];
            float cand_r = (rr & 2) ? s23 : s01;
            float diag_r = shfl(cand_r, (rr << 1) | ((rr >= 4) ? 1 : 0));
            float invd = rcpa(diag_r);
            if (lane < 16) {
                st4(&X2[rr * 20 + h * 8],
                    make_float4(rhs[0] * invd, rhs[1] * invd, rhs[2] * invd, rhs[3] * invd));
                st4(&X2[rr * 20 + h * 8 + 4],
                    make_float4(rhs[4] * invd, rhs[5] * invd, rhs[6] * invd, rhs[7] * invd));
                #pragma unroll
                for (int j = 0; j < 8; ++j)
                    g_K2[t * 128 + (h * 8 + j) * 8 + rr] = rhs[j] * invd;
            }
        }
        __syncwarp();

        // P_f = PP - K*(H*PP);  (H*PP)[q][j] = PHt[j][q]
        {
            float kq[8];
            #pragma unroll
            for (int q = 0; q < 8; ++q) kq[q] = X2[q * 20 + row];
            float n[8];
            #pragma unroll
            for (int j = 0; j < 8; ++j) {
                float4 p0 = ld4(&PHt[(j0 + j) * 8]);
                float4 p1 = ld4(&PHt[(j0 + j) * 8 + 4]);
                float v = a[j];
                v = fmaf(-kq[0], p0.x, v); v = fmaf(-kq[1], p0.y, v);
                v = fmaf(-kq[2], p0.z, v); v = fmaf(-kq[3], p0.w, v);
                v = fmaf(-kq[4], p1.x, v); v = fmaf(-kq[5], p1.y, v);
                v = fmaf(-kq[6], p1.z, v); v = fmaf(-kq[7], p1.w, v);
                n[j] = v;
            }
            float4 v0 = make_float4(n[0], n[1], n[2], n[3]);
            float4 v1 = make_float4(n[4], n[5], n[6], n[7]);
            st4(&P[row * 20 + j0], v0);
            st4(&P[row * 20 + j0 + 4], v1);
            if (t < T - 1) {
                st4(&g_Pf[t * 256 + row * 16 + j0], v0);
                st4(&g_Pf[t * 256 + row * 16 + j0 + 4], v1);
            }
        }
        __syncwarp();
    }
}

// ============================================================================
// Kernel B: per-t matrix prep. Block per t (64 thr).
//  warp0: M_t = (I-K_tH)F, N_t = (I-K_tH)*DT*Bc
//  warp1 (t<T-1): G_t via 16x16 GJ, then U_t = I - G_tF, V_t = G_t*DT*Bc
// ============================================================================
__global__ __launch_bounds__(64) void kf_prep(
    const float* __restrict__ A, const float* __restrict__ Bc,
    const float* __restrict__ H, const float* __restrict__ Q)
{
    __shared__ float Fb[16 * 20], Ftb[16 * 20], Qb[16 * 20];
    __shared__ float Hb[8 * 20], Bcs[64], Gs[16 * 20];

    const int t = blockIdx.x;
    const int tid = threadIdx.x;
    const int wrp = tid >> 5, lane = tid & 31;

    for (int idx = tid; idx < 256; idx += 64) {
        int i = idx >> 4, k = idx & 15;
        float av = A[idx];
        float f = (i == k ? 1.0f : 0.0f) + DT * av;
        Fb[i * 20 + k] = f; Ftb[k * 20 + i] = f;
        Qb[i * 20 + k] = Q[idx];
    }
    for (int idx = tid; idx < 128; idx += 64)
        Hb[(idx >> 4) * 20 + (idx & 15)] = H[idx];
    Bcs[tid] = Bc[tid];
    __syncthreads();

    const int row = lane >> 1, h = lane & 1, j0 = h * 8;

    if (wrp == 0) {
        // ---- M, N for this t ----
        float kr[8];
        {
            float4 k0 = ld4(&g_K2[t * 128 + row * 8]);
            float4 k1 = ld4(&g_K2[t * 128 + row * 8 + 4]);
            kr[0] = k0.x; kr[1] = k0.y; kr[2] = k0.z; kr[3] = k0.w;
            kr[4] = k1.x; kr[5] = k1.y; kr[6] = k1.z; kr[7] = k1.w;
        }
        // C[row][jslice] = sum_q K[row][q] * H[q][j]
        float c[8];
        #pragma unroll
        for (int j = 0; j < 8; ++j) c[j] = 0.f;
        #pragma unroll
        for (int q = 0; q < 8; ++q) {
            float kv = kr[q];
            float4 h0 = ld4(&Hb[q * 20 + j0]);
            float4 h1 = ld4(&Hb[q * 20 + j0 + 4]);
            c[0] = fmaf(kv, h0.x, c[0]); c[1] = fmaf(kv, h0.y, c[1]);
            c[2] = fmaf(kv, h0.z, c[2]); c[3] = fmaf(kv, h0.w, c[3]);
            c[4] = fmaf(kv, h1.x, c[4]); c[5] = fmaf(kv, h1.y, c[5]);
            c[6] = fmaf(kv, h1.z, c[6]); c[7] = fmaf(kv, h1.w, c[7]);
        }
        float ck[16];
        #pragma unroll
        for (int j = 0; j < 8; ++j) {
            ck[j0 + j] = c[j];
            ck[(j0 ^ 8) + j] = shflx(c[j], 1);
        }
        // M slice = F - C*F
        float m[8];
        {
            float4 f0 = ld4(&Fb[row * 20 + j0]);
            float4 f1 = ld4(&Fb[row * 20 + j0 + 4]);
            m[0] = f0.x; m[1] = f0.y; m[2] = f0.z; m[3] = f0.w;
            m[4] = f1.x; m[5] = f1.y; m[6] = f1.z; m[7] = f1.w;
        }
        #pragma unroll
        for (int k = 0; k < 16; ++k) {
            float cv = ck[k];
            float4 f0 = ld4(&Fb[k * 20 + j0]);
            float4 f1 = ld4(&Fb[k * 20 + j0 + 4]);
            m[0] = fmaf(-cv, f0.x, m[0]); m[1] = fmaf(-cv, f0.y, m[1]);
            m[2] = fmaf(-cv, f0.z, m[2]); m[3] = fmaf(-cv, f0.w, m[3]);
            m[4] = fmaf(-cv, f1.x, m[4]); m[5] = fmaf(-cv, f1.y, m[5]);
            m[6] = fmaf(-cv, f1.z, m[6]); m[7] = fmaf(-cv, f1.w, m[7]);
        }
        st4(&g_M[t * 256 + row * 16 + j0],     make_float4(m[0], m[1], m[2], m[3]));
        st4(&g_M[t * 256 + row * 16 + j0 + 4], make_float4(m[4], m[5], m[6], m[7]));
        // N[row][c] = DT*(Bc[row][c] - sum_k ck[k]*Bc[k][c])
        if (h == 0) {
            float n[4];
            #pragma unroll
            for (int cc = 0; cc < 4; ++cc) {
                float acc = Bcs[row * 4 + cc];
                #pragma unroll
                for (int k = 0; k < 16; ++k) acc = fmaf(-ck[k], Bcs[k * 4 + cc], acc);
                n[cc] = DT * acc;
            }
            st4(&g_N[t * 64 + row * 4], make_float4(n[0], n[1], n[2], n[3]));
        }
    } else if (t < T - 1) {
        // ---- G_t, U_t, V_t ----
        float* Pf = Gs;   // reuse buffer: holds Pf first, then G
        for (int idx = lane; idx < 256; idx += 32)
            Pf[(idx >> 4) * 20 + (idx & 15)] = g_Pf[t * 256 + idx];
        __syncwarp();

        float frow[16];
        #pragma unroll
        for (int k = 0; k < 16; ++k) frow[k] = Fb[row * 20 + k];

        float a[8], w[8];
        #pragma unroll
        for (int j = 0; j < 8; ++j) w[j] = 0.0f;
        #pragma unroll
        for (int k = 0; k < 16; ++k) {
            float fv = frow[k];
            float4 p0 = ld4(&Pf[k * 20 + j0]);
            float4 p1 = ld4(&Pf[k * 20 + j0 + 4]);
            w[0] = fmaf(fv, p0.x, w[0]); w[1] = fmaf(fv, p0.y, w[1]);
            w[2] = fmaf(fv, p0.z, w[2]); w[3] = fmaf(fv, p0.w, w[3]);
            w[4] = fmaf(fv, p1.x, w[4]); w[5] = fmaf(fv, p1.y, w[5]);
            w[6] = fmaf(fv, p1.z, w[6]); w[7] = fmaf(fv, p1.w, w[7]);
        }
        {
            float wk[16];
            #pragma unroll
            for (int j = 0; j < 8; ++j) {
                wk[j0 + j] = w[j];
                wk[(j0 ^ 8) + j] = shflx(w[j], 1);
            }
            float4 q0 = ld4(&Qb[row * 20 + j0]);
            float4 q1 = ld4(&Qb[row * 20 + j0 + 4]);
            a[0] = q0.x; a[1] = q0.y; a[2] = q0.z; a[3] = q0.w;
            a[4] = q1.x; a[5] = q1.y; a[6] = q1.z; a[7] = q1.w;
            #pragma unroll
            for (int k = 0; k < 16; ++k) {
                float wv = wk[k];
                float4 f0 = ld4(&Ftb[k * 20 + j0]);
                float4 f1 = ld4(&Ftb[k * 20 + j0 + 4]);
                a[0] = fmaf(wv, f0.x, a[0]); a[1] = fmaf(wv, f0.y, a[1]);
                a[2] = fmaf(wv, f0.z, a[2]); a[3] = fmaf(wv, f0.w, a[3]);
                a[4] = fmaf(wv, f1.x, a[4]); a[5] = fmaf(wv, f1.y, a[5]);
                a[6] = fmaf(wv, f1.z, a[6]); a[7] = fmaf(wv, f1.w, a[7]);
            }
        }
        #pragma unroll
        for (int p = 0; p < 16; ++p) {
            const int hp = (p >= 8) ? 1 : 0;
            float cand = a[p & 7];
            float f_num = shfl(cand, (row << 1) | hp);
            float diag  = shfl(cand, (p << 1) | hp);
            const int src = (p << 1) | h;
            float pa[8], pw[8];
            #pragma unroll
            for (int j = 0; j < 8; ++j) { pa[j] = shfl(a[j], src); pw[j] = shfl(w[j], src); }
            float f = (row == p) ? 0.0f : f_num * rcpa(diag);
            #pragma unroll
            for (int j = 0; j < 8; ++j) {
                a[j] = fmaf(-f, pa[j], a[j]);
                w[j] = fmaf(-f, pw[j], w[j]);
            }
        }
        const int ri = row & 7;
        float s01 = (ri & 1) ? a[1] : a[0];
        float s23 = (ri & 1) ? a[3] : a[2];
        float s45 = (ri & 1) ? a[5] : a[4];
        float s67 = (ri & 1) ? a[7] : a[6];
        float t0 = (ri & 2) ? s23 : s01;
        float t1 = (ri & 2) ? s67 : s45;
        float cand_r = (ri & 4) ? t1 : t0;
        float diag_r = shfl(cand_r, (row << 1) | ((row >= 8) ? 1 : 0));
        float invd = rcpa(diag_r);
        __syncwarp();   // Pf reads done; safe to overwrite Gs
        // Gs row-major: lane holds G^T[row][j0+j] = G[j0+j][row]
        #pragma unroll
        for (int j = 0; j < 8; ++j)
            Gs[(j0 + j) * 20 + row] = w[j] * invd;
        __syncwarp();

        // store G rows
        {
            float4 g0 = ld4(&Gs[row * 20 + j0]);
            float4 g1 = ld4(&Gs[row * 20 + j0 + 4]);
            st4(&g_G[t * 256 + row * 16 + j0], g0);
            st4(&g_G[t * 256 + row * 16 + j0 + 4], g1);
        }
        // U = I - G F
        float gk[16];
        #pragma unroll
        for (int k = 0; k < 16; ++k) gk[k] = Gs[row * 20 + k];
        float u8[8];
        #pragma unroll
        for (int j = 0; j < 8; ++j) u8[j] = (row == j0 + j) ? 1.0f : 0.0f;
        #pragma unroll
        for (int k = 0; k < 16; ++k) {
            float gv = gk[k];
            float4 f0 = ld4(&Fb[k * 20 + j0]);
            float4 f1 = ld4(&Fb[k * 20 + j0 + 4]);
            u8[0] = fmaf(-gv, f0.x, u8[0]); u8[1] = fmaf(-gv, f0.y, u8[1]);
            u8[2] = fmaf(-gv, f0.z, u8[2]); u8[3] = fmaf(-gv, f0.w, u8[3]);
            u8[4] = fmaf(-gv, f1.x, u8[4]); u8[5] = fmaf(-gv, f1.y, u8[5]);
            u8[6] = fmaf(-gv, f1.z, u8[6]); u8[7] = fmaf(-gv, f1.w, u8[7]);
        }
        st4(&g_U[t * 256 + row * 16 + j0],     make_float4(u8[0], u8[1], u8[2], u8[3]));
        st4(&g_U[t * 256 + row * 16 + j0 + 4], make_float4(u8[4], u8[5], u8[6], u8[7]));
        // V = G * DT * Bc
        if (h == 0) {
            float v[4];
            #pragma unroll
            for (int cc = 0; cc < 4; ++cc) {
                float acc = 0.f;
                #pragma unroll
                for (int k = 0; k < 16; ++k) acc = fmaf(gk[k], Bcs[k * 4 + cc], acc);
                v[cc] = DT * acc;
            }
            st4(&g_V[t * 64 + row * 4], make_float4(v[0], v[1], v[2], v[3]));
        }
    }
}

// ============================================================================
// Kernel C: forward states. One batch per warp (halves duplicate).
// s_{t+1} = M_t s + (N_t u_t + K_t y_t); aff term computed a step ahead.
// ============================================================================
__global__ __launch_bounds__(256) void kf_states(
    const float* __restrict__ state0, const float* __restrict__ controls,
    const float* __restrict__ obs, float* __restrict__ out)
{
    const int b = blockIdx.x * 8 + (threadIdx.x >> 5);
    const int lane = threadIdx.x & 31;
    const int i = lane & 15;
    const size_t bT = (size_t)b * T;

    float s = state0[b * 16 + i];

    float Mc[16], aff;
    {
        float4 m0 = ld4(&g_M[i * 16]),     m1 = ld4(&g_M[i * 16 + 4]);
        float4 m2 = ld4(&g_M[i * 16 + 8]), m3 = ld4(&g_M[i * 16 + 12]);
        Mc[0] = m0.x; Mc[1] = m0.y; Mc[2] = m0.z; Mc[3] = m0.w;
        Mc[4] = m1.x; Mc[5] = m1.y; Mc[6] = m1.z; Mc[7] = m1.w;
        Mc[8] = m2.x; Mc[9] = m2.y; Mc[10] = m2.z; Mc[11] = m2.w;
        Mc[12] = m3.x; Mc[13] = m3.y; Mc[14] = m3.z; Mc[15] = m3.w;
        float4 k0 = ld4(&g_K2[i * 8]), k1 = ld4(&g_K2[i * 8 + 4]);
        float4 nn = ld4(&g_N[i * 4]);
        float u_c = (i < 4) ? controls[bT * 4 + i] : 0.f;
        float y_c = (i < 8) ? obs[bT * 8 + i] : 0.f;
        float acc = 0.f;
        acc = fmaf(nn.x, shfl16(u_c, 0), acc); acc = fmaf(nn.y, shfl16(u_c, 1), acc);
        acc = fmaf(nn.z, shfl16(u_c, 2), acc); acc = fmaf(nn.w, shfl16(u_c, 3), acc);
        acc = fmaf(k0.x, shfl16(y_c, 0), acc); acc = fmaf(k0.y, shfl16(y_c, 1), acc);
        acc = fmaf(k0.z, shfl16(y_c, 2), acc); acc = fmaf(k0.w, shfl16(y_c, 3), acc);
        acc = fmaf(k1.x, shfl16(y_c, 4), acc); acc = fmaf(k1.y, shfl16(y_c, 5), acc);
        acc = fmaf(k1.z, shfl16(y_c, 6), acc); acc = fmaf(k1.w, shfl16(y_c, 7), acc);
        aff = acc;
    }

    #pragma unroll 1
    for (int t = 0; t < T; ++t) {
        float Mn[16], affn = 0.f;
        if (t + 1 < T) {
            const float* mp = &g_M[(t + 1) * 256 + i * 16];
            float4 m0 = ld4(mp), m1 = ld4(mp + 4), m2 = ld4(mp + 8), m3 = ld4(mp + 12);
            Mn[0] = m0.x; Mn[1] = m0.y; Mn[2] = m0.z; Mn[3] = m0.w;
            Mn[4] = m1.x; Mn[5] = m1.y; Mn[6] = m1.z; Mn[7] = m1.w;
            Mn[8] = m2.x; Mn[9] = m2.y; Mn[10] = m2.z; Mn[11] = m2.w;
            Mn[12] = m3.x; Mn[13] = m3.y; Mn[14] = m3.z; Mn[15] = m3.w;
            float4 k0 = ld4(&g_K2[(t + 1) * 128 + i * 8]);
            float4 k1 = ld4(&g_K2[(t + 1) * 128 + i * 8 + 4]);
            float4 nn = ld4(&g_N[(t + 1) * 64 + i * 4]);
            float u_n = (i < 4) ? controls[(bT + t + 1) * 4 + i] : 0.f;
            float y_n = (i < 8) ? obs[(bT + t + 1) * 8 + i] : 0.f;
            float acc = 0.f;
            acc = fmaf(nn.x, shfl16(u_n, 0), acc); acc = fmaf(nn.y, shfl16(u_n, 1), acc);
            acc = fmaf(nn.z, shfl16(u_n, 2), acc); acc = fmaf(nn.w, shfl16(u_n, 3), acc);
            acc = fmaf(k0.x, shfl16(y_n, 0), acc); acc = fmaf(k0.y, shfl16(y_n, 1), acc);
            acc = fmaf(k0.z, shfl16(y_n, 2), acc); acc = fmaf(k0.w, shfl16(y_n, 3), acc);
            acc = fmaf(k1.x, shfl16(y_n, 4), acc); acc = fmaf(k1.y, shfl16(y_n, 5), acc);
            acc = fmaf(k1.z, shfl16(y_n, 6), acc); acc = fmaf(k1.w, shfl16(y_n, 7), acc);
            affn = acc;
        }
        // chain: s' = M s + aff (two accumulators)
        float a0 = aff, a1 = 0.f;
        #pragma unroll
        for (int k = 0; k < 8; ++k) {
            a0 = fmaf(Mc[2 * k],     shfl16(s, 2 * k),     a0);
            a1 = fmaf(Mc[2 * k + 1], shfl16(s, 2 * k + 1), a1);
        }
        s = a0 + a1;
        if (lane < 16) out[(bT + t) * NS + i] = s;
        #pragma unroll
        for (int k = 0; k < 16; ++k) Mc[k] = Mn[k];
        aff = affn;
    }
}

// ============================================================================
// Kernel D: b[b][t] = U_t s_f[b][t] - V_t u[b][t+1].  Fully parallel,
// one (b,t) task per half-warp.
// ============================================================================
__global__ __launch_bounds__(256) void kf_bprep(
    const float* __restrict__ controls, const float* __restrict__ out)
{
    const int gw = blockIdx.x * 8 + (threadIdx.x >> 5);
    const int lane = threadIdx.x & 31;
    const int task = gw * 2 + (lane >> 4);       // 0 .. 2048*127-1
    const int b = task / (T - 1);
    const int t = task - b * (T - 1);
    const int i = lane & 15;

    float s = out[((size_t)b * T + t) * NS + i];
    float u_c = (i < 4) ? controls[((size_t)b * T + t + 1) * 4 + i] : 0.f;

    const float* up = &g_U[t * 256 + i * 16];
    float4 u0 = ld4(up), u1 = ld4(up + 4), u2 = ld4(up + 8), u3 = ld4(up + 12);
    float4 vv = ld4(&g_V[t * 64 + i * 4]);

    float a0 = 0.f, a1 = 0.f;
    a0 = fmaf(u0.x, shfl16(s, 0), a0);  a1 = fmaf(u0.y, shfl16(s, 1), a1);
    a0 = fmaf(u0.z, shfl16(s, 2), a0);  a1 = fmaf(u0.w, shfl16(s, 3), a1);
    a0 = fmaf(u1.x, shfl16(s, 4), a0);  a1 = fmaf(u1.y, shfl16(s, 5), a1);
    a0 = fmaf(u1.z, shfl16(s, 6), a0);  a1 = fmaf(u1.w, shfl16(s, 7), a1);
    a0 = fmaf(u2.x, shfl16(s, 8), a0);  a1 = fmaf(u2.y, shfl16(s, 9), a1);
    a0 = fmaf(u2.z, shfl16(s, 10), a0); a1 = fmaf(u2.w, shfl16(s, 11), a1);
    a0 = fmaf(u3.x, shfl16(s, 12), a0); a1 = fmaf(u3.y, shfl16(s, 13), a1);
    a0 = fmaf(u3.z, shfl16(s, 14), a0); a1 = fmaf(u3.w, shfl16(s, 15), a1);
    a0 = fmaf(-vv.x, shfl16(u_c, 0), a0); a1 = fmaf(-vv.y, shfl16(u_c, 1), a1);
    a0 = fmaf(-vv.z, shfl16(u_c, 2), a0); a1 = fmaf(-vv.w, shfl16(u_c, 3), a1);

    g_B[((size_t)b * (T - 1) + t) * NS + i] = a0 + a1;
}

// ============================================================================
// Kernel E: backward smoother. One batch per warp; ss = G_t ss + b_t.
// ============================================================================
__global__ __launch_bounds__(256) void kf_backward(float* __restrict__ out)
{
    const int b = blockIdx.x * 8 + (threadIdx.x >> 5);
    const int lane = threadIdx.x & 31;
    const int i = lane & 15;
    const size_t bT = (size_t)b * T;
    const size_t bB = (size_t)b * (T - 1);

    float ss = out[(bT + T - 1) * NS + i];

    float Gc[16], bc;
    {
        const float* gp = &g_G[(T - 2) * 256 + i * 16];
        float4 g0 = ld4(gp), g1 = ld4(gp + 4), g2 = ld4(gp + 8), g3 = ld4(gp + 12);
        Gc[0] = g0.x; Gc[1] = g0.y; Gc[2] = g0.z; Gc[3] = g0.w;
        Gc[4] = g1.x; Gc[5] = g1.y; Gc[6] = g1.z; Gc[7] = g1.w;
        Gc[8] = g2.x; Gc[9] = g2.y; Gc[10] = g2.z; Gc[11] = g2.w;
        Gc[12] = g3.x; Gc[13] = g3.y; Gc[14] = g3.z; Gc[15] = g3.w;
        bc = g_B[(bB + T - 2) * NS + i];
    }

    #pragma unroll 1
    for (int t = T - 2; t >= 0; --t) {
        float Gn[16], bn = 0.f;
        if (t > 0) {
            const float* gp = &g_G[(t - 1) * 256 + i * 16];
            float4 g0 = ld4(gp), g1 = ld4(gp + 4), g2 = ld4(gp + 8), g3 = ld4(gp + 12);
            Gn[0] = g0.x; Gn[1] = g0.y; Gn[2] = g0.z; Gn[3] = g0.w;
            Gn[4] = g1.x; Gn[5] = g1.y; Gn[6] = g1.z; Gn[7] = g1.w;
            Gn[8] = g2.x; Gn[9] = g2.y; Gn[10] = g2.z; Gn[11] = g2.w;
            Gn[12] = g3.x; Gn[13] = g3.y; Gn[14] = g3.z; Gn[15] = g3.w;
            bn = g_B[(bB + t - 1) * NS + i];
        }
        float a0 = bc, a1 = 0.f;
        #pragma unroll
        for (int k = 0; k < 8; ++k) {
            a0 = fmaf(Gc[2 * k],     shfl16(ss, 2 * k),     a0);
            a1 = fmaf(Gc[2 * k + 1], shfl16(ss, 2 * k + 1), a1);
        }
        ss = a0 + a1;
        if (lane < 16) out[(bT + t) * NS + i] = ss;
        #pragma unroll
        for (int k = 0; k < 16; ++k) Gc[k] = Gn[k];
        bc = bn;
    }
}

extern "C" void kernel_launch(void* const* d_in, const int* in_sizes, int n_in,
                              void* d_out, int out_size) {
    (void)in_sizes; (void)n_in; (void)out_size;
    const float* state0   = (const float*)d_in[0];
    const float* P0       = (const float*)d_in[1];
    const float* controls = (const float*)d_in[2];
    const float* obs      = (const float*)d_in[3];
    const float* A        = (const float*)d_in[4];
    const float* Bc       = (const float*)d_in[5];
    const float* H        = (const float*)d_in[6];
    const float* Q        = (const float*)d_in[7];
    const float* R        = (const float*)d_in[8];
    float* out = (float*)d_out;

    kf_gains<<<1, 32>>>(P0, A, H, Q, R);
    kf_prep<<<T, 64>>>(A, Bc, H, Q);
    kf_states<<<BATCH / 8, 256>>>(state0, controls, obs, out);
    kf_bprep<<<BATCH * (T - 1) / 16, 256>>>(controls, out);
    kf_backward<<<BATCH / 8, 256>>>(out);
}

// round 11
// speedup vs baseline: 1.4311x; 1.4311x over previous
#include <cuda_runtime.h>

#define BATCH 2048
#define T 128
#define NS 16
#define MS 8
#define CS 4
#define DT 0.01f

// Batch-independent tables (L2-resident).
__device__ float g_K2[T * NS * MS];             // K[t][i][q]  (row-major per t)
__device__ float g_Pf[(T - 1) * NS * NS];       // P_f[t]
__device__ float g_G[(T - 1) * NS * NS];        // G[t][i][j]  (row-major per t)
__device__ float g_sp[(size_t)BATCH * T * NS];  // predicted states (t>=1 used)

__device__ __forceinline__ float4 ld4(const float* p) { return *reinterpret_cast<const float4*>(p); }
__device__ __forceinline__ void st4(float* p, float4 v) { *reinterpret_cast<float4*>(p) = v; }
__device__ __forceinline__ float rcpa(float x) { float y; asm("rcp.approx.f32 %0, %1;" : "=f"(y) : "f"(x)); return y; }
__device__ __forceinline__ float shfl(float v, int s) { return __shfl_sync(0xffffffffu, v, s); }
__device__ __forceinline__ float shflx(float v, int m) { return __shfl_xor_sync(0xffffffffu, v, m); }
__device__ __forceinline__ float shfl16(float v, int s) { return __shfl_sync(0xffffffffu, v, s, 16); }

// ============================================================================
// Kernel A: batch-independent Riccati recursion (ONE warp, serial over T).
// ============================================================================
__global__ __launch_bounds__(32) void kf_gains(
    const float* __restrict__ P0, const float* __restrict__ A,
    const float* __restrict__ H, const float* __restrict__ Q,
    const float* __restrict__ R)
{
    __shared__ float Fb[16 * 20], Ftb[16 * 20], Qb[16 * 20];
    __shared__ float Hb[8 * 20], Ht[16 * 8], Rb[64];
    __shared__ float P[16 * 20], PHt[16 * 8], X2[8 * 20];

    const int lane = threadIdx.x;
    for (int idx = lane; idx < 256; idx += 32) {
        int i = idx >> 4, k = idx & 15;
        float a = A[idx];
        float f = (i == k ? 1.0f : 0.0f) + DT * a;
        Fb[i * 20 + k] = f; Ftb[k * 20 + i] = f;
        Qb[i * 20 + k] = Q[idx];
        P[i * 20 + k] = P0[idx];
    }
    for (int idx = lane; idx < 128; idx += 32) {
        int q = idx >> 4, k = idx & 15;
        float h = H[idx];
        Hb[q * 20 + k] = h; Ht[k * 8 + q] = h;
    }
    for (int idx = lane; idx < 64; idx += 32) Rb[idx] = R[idx];
    __syncwarp();

    const int row = lane >> 1, h = lane & 1, j0 = h * 8;
    const int rr = row & 7;

    float frow[16];
    #pragma unroll
    for (int k = 0; k < 16; ++k) frow[k] = Fb[row * 20 + k];

    float a[8], w[8];

    for (int t = 0; t < T; ++t) {
        // W = F * P
        #pragma unroll
        for (int j = 0; j < 8; ++j) w[j] = 0.0f;
        #pragma unroll
        for (int k = 0; k < 16; ++k) {
            float fv = frow[k];
            float4 p0 = ld4(&P[k * 20 + j0]);
            float4 p1 = ld4(&P[k * 20 + j0 + 4]);
            w[0] = fmaf(fv, p0.x, w[0]); w[1] = fmaf(fv, p0.y, w[1]);
            w[2] = fmaf(fv, p0.z, w[2]); w[3] = fmaf(fv, p0.w, w[3]);
            w[4] = fmaf(fv, p1.x, w[4]); w[5] = fmaf(fv, p1.y, w[5]);
            w[6] = fmaf(fv, p1.z, w[6]); w[7] = fmaf(fv, p1.w, w[7]);
        }

        // PP = W * F^T + Q  (kept in regs a[])
        {
            float wk[16];
            #pragma unroll
            for (int j = 0; j < 8; ++j) {
                wk[j0 + j] = w[j];
                wk[(j0 ^ 8) + j] = shflx(w[j], 1);
            }
            float4 q0 = ld4(&Qb[row * 20 + j0]);
            float4 q1 = ld4(&Qb[row * 20 + j0 + 4]);
            a[0] = q0.x; a[1] = q0.y; a[2] = q0.z; a[3] = q0.w;
            a[4] = q1.x; a[5] = q1.y; a[6] = q1.z; a[7] = q1.w;
            #pragma unroll
            for (int k = 0; k < 16; ++k) {
                float wv = wk[k];
                float4 f0 = ld4(&Ftb[k * 20 + j0]);
                float4 f1 = ld4(&Ftb[k * 20 + j0 + 4]);
                a[0] = fmaf(wv, f0.x, a[0]); a[1] = fmaf(wv, f0.y, a[1]);
                a[2] = fmaf(wv, f0.z, a[2]); a[3] = fmaf(wv, f0.w, a[3]);
                a[4] = fmaf(wv, f1.x, a[4]); a[5] = fmaf(wv, f1.y, a[5]);
                a[6] = fmaf(wv, f1.z, a[6]); a[7] = fmaf(wv, f1.w, a[7]);
            }
        }

        // PHt[i][q] = sum_k PP[i][k] * H[q][k]
        {
            float pk[16];
            #pragma unroll
            for (int j = 0; j < 8; ++j) {
                pk[j0 + j] = a[j];
                pk[(j0 ^ 8) + j] = shflx(a[j], 1);
            }
            const int qh = h * 4;
            float4 acc = make_float4(0.f, 0.f, 0.f, 0.f);
            #pragma unroll
            for (int k = 0; k < 16; ++k) {
                float p = pk[k];
                float4 hv = ld4(&Ht[k * 8 + qh]);
                acc.x = fmaf(p, hv.x, acc.x); acc.y = fmaf(p, hv.y, acc.y);
                acc.z = fmaf(p, hv.z, acc.z); acc.w = fmaf(p, hv.w, acc.w);
            }
            st4(&PHt[row * 8 + qh], acc);
        }
        __syncwarp();

        // S rows + RHS into registers
        float s4[4], rhs[8];
        {
            const int ch = h * 4;
            s4[0] = Rb[rr * 8 + ch];     s4[1] = Rb[rr * 8 + ch + 1];
            s4[2] = Rb[rr * 8 + ch + 2]; s4[3] = Rb[rr * 8 + ch + 3];
            #pragma unroll
            for (int k = 0; k < 16; ++k) {
                float hv = Hb[rr * 20 + k];
                float4 ph = ld4(&PHt[k * 8 + ch]);
                s4[0] = fmaf(hv, ph.x, s4[0]); s4[1] = fmaf(hv, ph.y, s4[1]);
                s4[2] = fmaf(hv, ph.z, s4[2]); s4[3] = fmaf(hv, ph.w, s4[3]);
            }
            #pragma unroll
            for (int j = 0; j < 8; ++j)
                rhs[j] = PHt[(h * 8 + j) * 8 + rr];
        }

        // GJ solve S * X2 = PHt^T (8x8); K = X2^T
        {
            #pragma unroll
            for (int p = 0; p < 8; ++p) {
                const int hp = (p >= 4) ? 1 : 0;
                float cand = s4[p & 3];
                float f_num = shfl(cand, (rr << 1) | hp);
                float diag  = shfl(cand, (p << 1) | hp);
                const int src = (p << 1) | h;
                float ps0 = shfl(s4[0], src), ps1 = shfl(s4[1], src);
                float ps2 = shfl(s4[2], src), ps3 = shfl(s4[3], src);
                float pr[8];
                #pragma unroll
                for (int j = 0; j < 8; ++j) pr[j] = shfl(rhs[j], src);
                float f = (rr == p) ? 0.0f : f_num * rcpa(diag);
                s4[0] = fmaf(-f, ps0, s4[0]); s4[1] = fmaf(-f, ps1, s4[1]);
                s4[2] = fmaf(-f, ps2, s4[2]); s4[3] = fmaf(-f, ps3, s4[3]);
                #pragma unroll
                for (int j = 0; j < 8; ++j) rhs[j] = fmaf(-f, pr[j], rhs[j]);
            }
            float s01 = (rr & 1) ? s4[1] : s4[0];
            float s23 = (rr & 1) ? s4[3] : s4[2];
            float cand_r = (rr & 2) ? s23 : s01;
            float diag_r = shfl(cand_r, (rr << 1) | ((rr >= 4) ? 1 : 0));
            float invd = rcpa(diag_r);
            if (lane < 16) {
                st4(&X2[rr * 20 + h * 8],
                    make_float4(rhs[0] * invd, rhs[1] * invd, rhs[2] * invd, rhs[3] * invd));
                st4(&X2[rr * 20 + h * 8 + 4],
                    make_float4(rhs[4] * invd, rhs[5] * invd, rhs[6] * invd, rhs[7] * invd));
                // transposed: g_K2[t][i][q] = K[i][q] = X2[rr][i], i = h*8+j, q = rr
                #pragma unroll
                for (int j = 0; j < 8; ++j)
                    g_K2[t * 128 + (h * 8 + j) * 8 + rr] = rhs[j] * invd;
            }
        }
        __syncwarp();

        // P_f = PP - K*(H*PP);  (H*PP)[q][j] = PHt[j][q]  (PP symmetric)
        {
            float kq[8];
            #pragma unroll
            for (int q = 0; q < 8; ++q) kq[q] = X2[q * 20 + row];
            float n[8];
            #pragma unroll
            for (int j = 0; j < 8; ++j) {
                float4 p0 = ld4(&PHt[(j0 + j) * 8]);
                float4 p1 = ld4(&PHt[(j0 + j) * 8 + 4]);
                float v = a[j];
                v = fmaf(-kq[0], p0.x, v); v = fmaf(-kq[1], p0.y, v);
                v = fmaf(-kq[2], p0.z, v); v = fmaf(-kq[3], p0.w, v);
                v = fmaf(-kq[4], p1.x, v); v = fmaf(-kq[5], p1.y, v);
                v = fmaf(-kq[6], p1.z, v); v = fmaf(-kq[7], p1.w, v);
                n[j] = v;
            }
            float4 v0 = make_float4(n[0], n[1], n[2], n[3]);
            float4 v1 = make_float4(n[4], n[5], n[6], n[7]);
            st4(&P[row * 20 + j0], v0);
            st4(&P[row * 20 + j0 + 4], v1);
            if (t < T - 1) {
                st4(&g_Pf[t * 256 + row * 16 + j0], v0);
                st4(&g_Pf[t * 256 + row * 16 + j0 + 4], v1);
            }
        }
        __syncwarp();
    }
}

// ============================================================================
// Kernel B: smoother gains, T-1 parallel warps. G[t] = (P_f F^T P_p[t+1]^-1)
// stored row-major: g_G[t][i][j].
// ============================================================================
__global__ __launch_bounds__(32) void kf_smoother_gains(
    const float* __restrict__ A, const float* __restrict__ Q)
{
    __shared__ float Fb[16 * 20], Ftb[16 * 20], Qb[16 * 20], Pf[16 * 20];
    const int t = blockIdx.x;
    const int lane = threadIdx.x;

    for (int idx = lane; idx < 256; idx += 32) {
        int i = idx >> 4, k = idx & 15;
        float av = A[idx];
        float f = (i == k ? 1.0f : 0.0f) + DT * av;
        Fb[i * 20 + k] = f; Ftb[k * 20 + i] = f;
        Qb[i * 20 + k] = Q[idx];
        Pf[i * 20 + k] = g_Pf[t * 256 + idx];
    }
    __syncwarp();

    const int row = lane >> 1, h = lane & 1, j0 = h * 8;
    float frow[16];
    #pragma unroll
    for (int k = 0; k < 16; ++k) frow[k] = Fb[row * 20 + k];

    float a[8], w[8];
    #pragma unroll
    for (int j = 0; j < 8; ++j) w[j] = 0.0f;
    #pragma unroll
    for (int k = 0; k < 16; ++k) {
        float fv = frow[k];
        float4 p0 = ld4(&Pf[k * 20 + j0]);
        float4 p1 = ld4(&Pf[k * 20 + j0 + 4]);
        w[0] = fmaf(fv, p0.x, w[0]); w[1] = fmaf(fv, p0.y, w[1]);
        w[2] = fmaf(fv, p0.z, w[2]); w[3] = fmaf(fv, p0.w, w[3]);
        w[4] = fmaf(fv, p1.x, w[4]); w[5] = fmaf(fv, p1.y, w[5]);
        w[6] = fmaf(fv, p1.z, w[6]); w[7] = fmaf(fv, p1.w, w[7]);
    }
    {
        float wk[16];
        #pragma unroll
        for (int j = 0; j < 8; ++j) {
            wk[j0 + j] = w[j];
            wk[(j0 ^ 8) + j] = shflx(w[j], 1);
        }
        float4 q0 = ld4(&Qb[row * 20 + j0]);
        float4 q1 = ld4(&Qb[row * 20 + j0 + 4]);
        a[0] = q0.x; a[1] = q0.y; a[2] = q0.z; a[3] = q0.w;
        a[4] = q1.x; a[5] = q1.y; a[6] = q1.z; a[7] = q1.w;
        #pragma unroll
        for (int k = 0; k < 16; ++k) {
            float wv = wk[k];
            float4 f0 = ld4(&Ftb[k * 20 + j0]);
            float4 f1 = ld4(&Ftb[k * 20 + j0 + 4]);
            a[0] = fmaf(wv, f0.x, a[0]); a[1] = fmaf(wv, f0.y, a[1]);
            a[2] = fmaf(wv, f0.z, a[2]); a[3] = fmaf(wv, f0.w, a[3]);
            a[4] = fmaf(wv, f1.x, a[4]); a[5] = fmaf(wv, f1.y, a[5]);
            a[6] = fmaf(wv, f1.z, a[6]); a[7] = fmaf(wv, f1.w, a[7]);
        }
    }
    #pragma unroll
    for (int p = 0; p < 16; ++p) {
        const int hp = (p >= 8) ? 1 : 0;
        float cand = a[p & 7];
        float f_num = shfl(cand, (row << 1) | hp);
        float diag  = shfl(cand, (p << 1) | hp);
        const int src = (p << 1) | h;
        float pa[8], pw[8];
        #pragma unroll
        for (int j = 0; j < 8; ++j) { pa[j] = shfl(a[j], src); pw[j] = shfl(w[j], src); }
        float f = (row == p) ? 0.0f : f_num * rcpa(diag);
        #pragma unroll
        for (int j = 0; j < 8; ++j) {
            a[j] = fmaf(-f, pa[j], a[j]);
            w[j] = fmaf(-f, pw[j], w[j]);
        }
    }
    const int ri = row & 7;
    float s01 = (ri & 1) ? a[1] : a[0];
    float s23 = (ri & 1) ? a[3] : a[2];
    float s45 = (ri & 1) ? a[5] : a[4];
    float s67 = (ri & 1) ? a[7] : a[6];
    float t0 = (ri & 2) ? s23 : s01;
    float t1 = (ri & 2) ? s67 : s45;
    float cand_r = (ri & 4) ? t1 : t0;
    float diag_r = shfl(cand_r, (row << 1) | ((row >= 8) ? 1 : 0));
    float invd = rcpa(diag_r);
    // lane holds X[row][j0+j] with X = G^T; store G rows: g_G[t][i=j0+j][row]
    #pragma unroll
    for (int j = 0; j < 8; ++j)
        g_G[t * 256 + (j0 + j) * 16 + row] = w[j] * invd;
}

// ============================================================================
// Kernel C: forward state filter (R6 structure; K via 2x LDG.128).
// ============================================================================
__global__ __launch_bounds__(128) void kf_states(
    const float* __restrict__ state0, const float* __restrict__ controls,
    const float* __restrict__ obs, const float* __restrict__ A,
    const float* __restrict__ Bc, const float* __restrict__ H,
    float* __restrict__ out)
{
    const int L = threadIdx.x & 31;
    const int gw = blockIdx.x * 4 + (threadIdx.x >> 5);
    const int b = gw * 2 + (L >> 4);
    const int i = L & 15;

    float arow[16], hrow[16], brow[4];
    #pragma unroll
    for (int k = 0; k < 16; ++k) arow[k] = A[i * 16 + k];
    #pragma unroll
    for (int k = 0; k < 16; ++k) hrow[k] = H[(i & 7) * 16 + k];
    #pragma unroll
    for (int c = 0; c < 4; ++c) brow[c] = Bc[i * 4 + c];

    float s = state0[b * 16 + i];
    float u_c = (i < 4) ? controls[(size_t)b * T * 4 + i] : 0.0f;
    float y_c = (i < 8) ? obs[(size_t)b * T * 8 + i] : 0.0f;
    float4 k0 = ld4(&g_K2[i * 8]);
    float4 k1 = ld4(&g_K2[i * 8 + 4]);

    #pragma unroll 1
    for (int t = 0; t < T; ++t) {
        float u_n = 0.0f, y_n = 0.0f;
        float4 k0n = make_float4(0.f, 0.f, 0.f, 0.f);
        float4 k1n = make_float4(0.f, 0.f, 0.f, 0.f);
        if (t + 1 < T) {
            u_n = (i < 4) ? controls[((size_t)b * T + t + 1) * 4 + i] : 0.0f;
            y_n = (i < 8) ? obs[((size_t)b * T + t + 1) * 8 + i] : 0.0f;
            k0n = ld4(&g_K2[(t + 1) * 128 + i * 8]);
            k1n = ld4(&g_K2[(t + 1) * 128 + i * 8 + 4]);
        }

        // s_p = s + DT*(A s + Bc u)
        float a0 = 0.0f, a1 = 0.0f;
        #pragma unroll
        for (int k = 0; k < 8; ++k) {
            a0 = fmaf(arow[k], shfl16(s, k), a0);
            a1 = fmaf(arow[k + 8], shfl16(s, k + 8), a1);
        }
        #pragma unroll
        for (int c = 0; c < 4; ++c) a0 = fmaf(brow[c], shfl16(u_c, c), a0);
        float sp = s + DT * (a0 + a1);
        if (t > 0) g_sp[((size_t)b * T + t) * NS + i] = sp;

        // innov = y - H s_p
        float h0 = 0.0f, h1 = 0.0f;
        #pragma unroll
        for (int k = 0; k < 8; ++k) {
            h0 = fmaf(hrow[k], shfl16(sp, k), h0);
            h1 = fmaf(hrow[k + 8], shfl16(sp, k + 8), h1);
        }
        float iv = y_c - (h0 + h1);

        // s = s_p + K innov
        float acc = sp;
        acc = fmaf(k0.x, shfl16(iv, 0), acc);
        acc = fmaf(k0.y, shfl16(iv, 1), acc);
        acc = fmaf(k0.z, shfl16(iv, 2), acc);
        acc = fmaf(k0.w, shfl16(iv, 3), acc);
        acc = fmaf(k1.x, shfl16(iv, 4), acc);
        acc = fmaf(k1.y, shfl16(iv, 5), acc);
        acc = fmaf(k1.z, shfl16(iv, 6), acc);
        acc = fmaf(k1.w, shfl16(iv, 7), acc);
        s = acc;
        out[((size_t)b * T + t) * NS + i] = s;
        u_c = u_n; y_c = y_n; k0 = k0n; k1 = k1n;
    }
}

// ============================================================================
// Kernel D: backward smoother (R6 structure; G rows via 4x LDG.128).
// ============================================================================
__global__ __launch_bounds__(128) void kf_backward(float* __restrict__ out)
{
    const int L = threadIdx.x & 31;
    const int gw = blockIdx.x * 4 + (threadIdx.x >> 5);
    const int b = gw * 2 + (L >> 4);
    const int i = L & 15;

    float ss = out[((size_t)b * T + (T - 1)) * NS + i];
    float xc[16];
    {
        const float* gp = &g_G[(T - 2) * 256 + i * 16];
        float4 g0 = ld4(gp), g1 = ld4(gp + 4), g2 = ld4(gp + 8), g3 = ld4(gp + 12);
        xc[0] = g0.x; xc[1] = g0.y; xc[2] = g0.z; xc[3] = g0.w;
        xc[4] = g1.x; xc[5] = g1.y; xc[6] = g1.z; xc[7] = g1.w;
        xc[8] = g2.x; xc[9] = g2.y; xc[10] = g2.z; xc[11] = g2.w;
        xc[12] = g3.x; xc[13] = g3.y; xc[14] = g3.z; xc[15] = g3.w;
    }
    float spn_c = g_sp[((size_t)b * T + (T - 1)) * NS + i];
    float sf_c  = out[((size_t)b * T + (T - 2)) * NS + i];

    #pragma unroll 1
    for (int t = T - 2; t >= 0; --t) {
        float xn[16]; float spn_n = 0.0f, sf_n = 0.0f;
        if (t > 0) {
            const float* gp = &g_G[(t - 1) * 256 + i * 16];
            float4 g0 = ld4(gp), g1 = ld4(gp + 4), g2 = ld4(gp + 8), g3 = ld4(gp + 12);
            xn[0] = g0.x; xn[1] = g0.y; xn[2] = g0.z; xn[3] = g0.w;
            xn[4] = g1.x; xn[5] = g1.y; xn[6] = g1.z; xn[7] = g1.w;
            xn[8] = g2.x; xn[9] = g2.y; xn[10] = g2.z; xn[11] = g2.w;
            xn[12] = g3.x; xn[13] = g3.y; xn[14] = g3.z; xn[15] = g3.w;
            spn_n = g_sp[((size_t)b * T + t) * NS + i];
            sf_n  = out[((size_t)b * T + t - 1) * NS + i];
        }
        float d = ss - spn_c;
        float m0 = 0.0f, m1 = 0.0f;
        #pragma unroll
        for (int j = 0; j < 8; ++j) {
            m0 = fmaf(shfl16(d, j), xc[j], m0);
            m1 = fmaf(shfl16(d, j + 8), xc[j + 8], m1);
        }
        ss = sf_c + m0 + m1;
        out[((size_t)b * T + t) * NS + i] = ss;
        if (t > 0) {
            #pragma unroll
            for (int j = 0; j < 16; ++j) xc[j] = xn[j];
            spn_c = spn_n; sf_c = sf_n;
        }
    }
}

extern "C" void kernel_launch(void* const* d_in, const int* in_sizes, int n_in,
                              void* d_out, int out_size) {
    (void)in_sizes; (void)n_in; (void)out_size;
    const float* state0   = (const float*)d_in[0];
    const float* P0       = (const float*)d_in[1];
    const float* controls = (const float*)d_in[2];
    const float* obs      = (const float*)d_in[3];
    const float* A        = (const float*)d_in[4];
    const float* Bc       = (const float*)d_in[5];
    const float* H        = (const float*)d_in[6];
    const float* Q        = (const float*)d_in[7];
    const float* R        = (const float*)d_in[8];
    float* out = (float*)d_out;

    kf_gains<<<1, 32>>>(P0, A, H, Q, R);
    kf_smoother_gains<<<T - 1, 32>>>(A, Q);
    kf_states<<<BATCH / 8, 128>>>(state0, controls, obs, A, Bc, H, out);
    kf_backward<<<BATCH / 8, 128>>>(out);
}